// round 4
// baseline (speedup 1.0000x reference)
#include <cuda_runtime.h>
#include <cstdint>

#define N_NODES 4096
#define D_IN    256
#define D_OUT   128
#define H_HEADS 4
#define NEG_SLOPE 0.2f
#define NWORDS  (N_NODES / 32)

typedef unsigned long long u64;

// ---------------- scratch (device globals; no allocation allowed) ----------------
__device__ float    g_h[H_HEADS * N_NODES * D_OUT];   // 8 MB   h[head][j][o]
__device__ unsigned g_mask[N_NODES * NWORDS];          // 2 MB   bit j of row i
__device__ float    g_si [H_HEADS * N_NODES];
__device__ float    g_Ei [H_HEADS * N_NODES];          // exp(s_i)
__device__ float    g_Ei2[H_HEADS * N_NODES];          // exp(0.2*s_i)
__device__ float4   g_jp [H_HEADS * N_NODES];          // (s_j, exp(s_j), exp(0.2*s_j), 0)

// ---------------- f32x2 helpers (Blackwell packed fp32) ----------------
__device__ __forceinline__ u64 packf2(float lo, float hi) {
    u64 r; asm("mov.b64 %0, {%1, %2};" : "=l"(r) : "f"(lo), "f"(hi)); return r;
}
__device__ __forceinline__ void unpackf2(u64 v, float& lo, float& hi) {
    asm("mov.b64 {%0, %1}, %2;" : "=f"(lo), "=f"(hi) : "l"(v));
}
__device__ __forceinline__ u64 fma2(u64 a, u64 b, u64 c) {
    u64 r; asm("fma.rn.f32x2 %0, %1, %2, %3;" : "=l"(r) : "l"(a), "l"(b), "l"(c)); return r;
}

// ---------------- kernel 1: bit-pack mask = (A>0) | eye ----------------
__global__ void pack_mask_kernel(const int* __restrict__ A) {
    int g    = blockIdx.x * blockDim.x + threadIdx.x;
    int lane = g & 31;
    int word = g >> 5;
    int row  = word >> 7;
    int jw   = word & 127;
    int j    = jw * 32 + lane;
    int v = (A[row * N_NODES + j] > 0) || (j == row);
    unsigned b = __ballot_sync(0xffffffffu, v);
    if (lane == 0) g_mask[word] = b;
}

// ---------------- kernel 2: h = x @ W per head (fp32 tiled GEMM) ----------------
__global__ __launch_bounds__(256) void h_gemm_kernel(const float* __restrict__ x,
                                                     const float* __restrict__ W) {
    __shared__ __align__(16) float xs[32][129];
    __shared__ __align__(16) float ws[32][128];
    int head    = blockIdx.y;
    int rowbase = blockIdx.x * 128;
    int tid = threadIdx.x;
    int tx  = tid & 15;
    int ty  = tid >> 4;
    int o0  = tx * 8;

    float acc[8][8];
#pragma unroll
    for (int u = 0; u < 8; u++)
#pragma unroll
        for (int i = 0; i < 8; i++) acc[u][i] = 0.f;

    const float* Wh = W + head * D_IN * D_OUT;

    for (int k0 = 0; k0 < D_IN; k0 += 32) {
        __syncthreads();
#pragma unroll
        for (int u = 0; u < 4; u++) {
            int e4  = tid + u * 256;
            int row = e4 >> 3, kq = e4 & 7;
            float4 v = *(const float4*)&x[(rowbase + row) * D_IN + k0 + kq * 4];
            xs[kq * 4 + 0][row] = v.x;
            xs[kq * 4 + 1][row] = v.y;
            xs[kq * 4 + 2][row] = v.z;
            xs[kq * 4 + 3][row] = v.w;
        }
#pragma unroll
        for (int u = 0; u < 4; u++) {
            int e4 = tid + u * 256;
            int kk = e4 >> 5, oq = e4 & 31;
            *(float4*)&ws[kk][oq * 4] = *(const float4*)&Wh[(k0 + kk) * D_OUT + oq * 4];
        }
        __syncthreads();
#pragma unroll
        for (int kk = 0; kk < 32; kk++) {
            float wv[8];
            *(float4*)&wv[0] = *(const float4*)&ws[kk][o0];
            *(float4*)&wv[4] = *(const float4*)&ws[kk][o0 + 4];
#pragma unroll
            for (int u = 0; u < 8; u++) {
                float xv = xs[kk][ty + u * 16];
#pragma unroll
                for (int i = 0; i < 8; i++) acc[u][i] += xv * wv[i];
            }
        }
    }
#pragma unroll
    for (int u = 0; u < 8; u++) {
        int row = rowbase + ty + u * 16;
        float* dst = &g_h[(head * N_NODES + row) * D_OUT + o0];
        *(float4*)&dst[0] = make_float4(acc[u][0], acc[u][1], acc[u][2], acc[u][3]);
        *(float4*)&dst[4] = make_float4(acc[u][4], acc[u][5], acc[u][6], acc[u][7]);
    }
}

// ---------------- kernel 3: s_i, s_j and separable exp factors ----------------
__global__ void sij_kernel(const float* __restrict__ a) {
    int head = blockIdx.y;
    int warp = threadIdx.x >> 5, lane = threadIdx.x & 31;
    int row  = blockIdx.x * 8 + warp;
    const float* hrow = &g_h[(head * N_NODES + row) * D_OUT];
    const float* ah   = a + head * 2 * D_OUT;
    float s1 = 0.f, s2 = 0.f;
#pragma unroll
    for (int u = 0; u < 4; u++) {
        int o = lane + u * 32;
        float hv = hrow[o];
        s1 += hv * ah[o];
        s2 += hv * ah[D_OUT + o];
    }
#pragma unroll
    for (int off = 16; off; off >>= 1) {
        s1 += __shfl_xor_sync(0xffffffffu, s1, off);
        s2 += __shfl_xor_sync(0xffffffffu, s2, off);
    }
    if (lane == 0) {
        g_si [head * N_NODES + row] = s1;
        g_Ei [head * N_NODES + row] = expf(s1);
        g_Ei2[head * N_NODES + row] = expf(NEG_SLOPE * s1);
        g_jp [head * N_NODES + row] = make_float4(s2, expf(s2), expf(NEG_SLOPE * s2), 0.f);
    }
}

// ---------------- kernel 4: fused masked-softmax aggregation ----------------
// R1 structure (proven reg budget: 128 threads, 2 rows x 32 cols / thread)
// + bank-conflict-free chunk stagger: c = (k + 2*tx) & 7
//   -> word offsets mod 32 are {4k, 4k+8, 4k+16, 4k+24}: disjoint bank groups.
__global__ __launch_bounds__(128) void agg_kernel(float* __restrict__ out) {
    __shared__ __align__(16) float  hsm[32 * 128];   // 32 j x 128 o tile
    __shared__ __align__(16) float4 psm[32];         // (sj, Ej, Ej2) per j

    int head    = blockIdx.y;
    int rowbase = blockIdx.x * 64;
    int tid = threadIdx.x;
    int tx  = tid & 3;
    int ty  = tid >> 2;
    int o0  = tx * 32;
    int sh  = tx * 2;                 // chunk stagger
    int r0  = rowbase + ty * 2, r1 = r0 + 1;

    float si0  = g_si [head * N_NODES + r0], si1  = g_si [head * N_NODES + r1];
    float Ei0  = g_Ei [head * N_NODES + r0], Ei1  = g_Ei [head * N_NODES + r1];
    float Ei20 = g_Ei2[head * N_NODES + r0], Ei21 = g_Ei2[head * N_NODES + r1];

    u64 acc0[16], acc1[16];
#pragma unroll
    for (int k = 0; k < 16; k++) { acc0[k] = 0ull; acc1[k] = 0ull; }
    float Z0 = 0.f, Z1 = 0.f;

    const float4* hsrc = (const float4*)&g_h[head * N_NODES * D_OUT];
    const float4* jpb  = &g_jp[head * N_NODES];

    for (int jt = 0; jt < N_NODES; jt += 32) {
        __syncthreads();
        {   // stage h tile (4096 floats = 1024 float4) + j params
            const float4* src = hsrc + jt * (D_OUT / 4);
            float4* dst = (float4*)hsm;
#pragma unroll
            for (int u = 0; u < 8; u++) dst[tid + u * 128] = src[tid + u * 128];
            if (tid < 32) psm[tid] = jpb[jt + tid];
        }
        __syncthreads();

        unsigned m0 = g_mask[r0 * NWORDS + (jt >> 5)];
        unsigned m1 = g_mask[r1 * NWORDS + (jt >> 5)];

#pragma unroll 8
        for (int jj = 0; jj < 32; jj++) {
            float4 p = psm[jj];
            float t0 = si0 + p.x;
            float v0 = (t0 > 0.f) ? (Ei0 * p.y) : (Ei20 * p.z);
            float w0 = ((m0 >> jj) & 1u) ? v0 : 0.f;
            float t1 = si1 + p.x;
            float v1 = (t1 > 0.f) ? (Ei1 * p.y) : (Ei21 * p.z);
            float w1 = ((m1 >> jj) & 1u) ? v1 : 0.f;
            Z0 += w0; Z1 += w1;
            u64 pw0 = packf2(w0, w0);
            u64 pw1 = packf2(w1, w1);
            const ulonglong2* hp = (const ulonglong2*)(hsm + jj * 128 + o0);
#pragma unroll
            for (int k = 0; k < 8; k++) {
                int c = (k + sh) & 7;                 // staggered chunk
                ulonglong2 hv = hp[c];
                acc0[2 * c    ] = fma2(pw0, hv.x, acc0[2 * c    ]);
                acc0[2 * c + 1] = fma2(pw0, hv.y, acc0[2 * c + 1]);
                acc1[2 * c    ] = fma2(pw1, hv.x, acc1[2 * c    ]);
                acc1[2 * c + 1] = fma2(pw1, hv.y, acc1[2 * c + 1]);
            }
        }
    }

    float inv0 = 1.f / Z0, inv1 = 1.f / Z1;
    float* out0 = out + (u64)r0 * (H_HEADS * D_OUT) + head * D_OUT + o0;
    float* out1 = out + (u64)r1 * (H_HEADS * D_OUT) + head * D_OUT + o0;
#pragma unroll
    for (int k = 0; k < 8; k++) {
        float a0, b0, c0, d0, a1f, b1f, c1f, d1f;
        unpackf2(acc0[2 * k],     a0, b0);
        unpackf2(acc0[2 * k + 1], c0, d0);
        unpackf2(acc1[2 * k],     a1f, b1f);
        unpackf2(acc1[2 * k + 1], c1f, d1f);
        *(float4*)&out0[4 * k] = make_float4(a0 * inv0, b0 * inv0, c0 * inv0, d0 * inv0);
        *(float4*)&out1[4 * k] = make_float4(a1f * inv1, b1f * inv1, c1f * inv1, d1f * inv1);
    }
}

// ---------------- launch ----------------
extern "C" void kernel_launch(void* const* d_in, const int* in_sizes, int n_in,
                              void* d_out, int out_size) {
    const float* x = (const float*)d_in[0];
    const int*   A = (const int*)  d_in[1];
    const float* W = (const float*)d_in[2];
    const float* a = (const float*)d_in[3];
    float* out = (float*)d_out;

    pack_mask_kernel<<<(N_NODES * N_NODES) / 256, 256>>>(A);
    h_gemm_kernel<<<dim3(N_NODES / 128, H_HEADS), 256>>>(x, W);
    sij_kernel<<<dim3(N_NODES / 8, H_HEADS), 256>>>(a);
    agg_kernel<<<dim3(N_NODES / 64, H_HEADS), 128>>>(out);
}

// round 6
// speedup vs baseline: 32.1373x; 32.1373x over previous
#include <cuda_runtime.h>
#include <cstdint>

#define N_NODES 4096
#define D_IN    256
#define D_OUT   128
#define H_HEADS 4
#define NEG_SLOPE 0.2f
#define NWORDS  (N_NODES / 32)

typedef unsigned long long u64;

// ---------------- scratch (device globals; no allocation allowed) ----------------
__device__ float    g_h[H_HEADS * N_NODES * D_OUT];   // 8 MB   h[head][j][o]
__device__ unsigned g_mask[N_NODES * NWORDS];          // 2 MB   bit j of row i
__device__ float    g_si [H_HEADS * N_NODES];
__device__ float    g_Ei [H_HEADS * N_NODES];          // exp(s_i)
__device__ float    g_Ei2[H_HEADS * N_NODES];          // exp(0.2*s_i)
__device__ float4   g_jp [H_HEADS * N_NODES];          // (s_j, exp(s_j), exp(0.2*s_j), 0)

// ---------------- f32x2 helpers (Blackwell packed fp32) ----------------
__device__ __forceinline__ u64 packf2(float lo, float hi) {
    u64 r; asm("mov.b64 %0, {%1, %2};" : "=l"(r) : "f"(lo), "f"(hi)); return r;
}
__device__ __forceinline__ void unpackf2(u64 v, float& lo, float& hi) {
    asm("mov.b64 {%0, %1}, %2;" : "=f"(lo), "=f"(hi) : "l"(v));
}
__device__ __forceinline__ u64 fma2(u64 a, u64 b, u64 c) {
    u64 r; asm("fma.rn.f32x2 %0, %1, %2, %3;" : "=l"(r) : "l"(a), "l"(b), "l"(c)); return r;
}

// ---------------- kernel 1: bit-pack mask = (A>0) | eye ----------------
__global__ void pack_mask_kernel(const int* __restrict__ A) {
    int g    = blockIdx.x * blockDim.x + threadIdx.x;
    int lane = g & 31;
    int word = g >> 5;
    int row  = word >> 7;
    int jw   = word & 127;
    int j    = jw * 32 + lane;
    int v = (A[row * N_NODES + j] > 0) || (j == row);
    unsigned b = __ballot_sync(0xffffffffu, v);
    if (lane == 0) g_mask[word] = b;
}

// ---------------- kernel 2: h = x @ W per head (fp32 tiled GEMM) ----------------
__global__ __launch_bounds__(256) void h_gemm_kernel(const float* __restrict__ x,
                                                     const float* __restrict__ W) {
    __shared__ __align__(16) float xs[32][129];
    __shared__ __align__(16) float ws[32][128];
    int head    = blockIdx.y;
    int rowbase = blockIdx.x * 128;
    int tid = threadIdx.x;
    int tx  = tid & 15;
    int ty  = tid >> 4;
    int o0  = tx * 8;

    float acc[8][8];
#pragma unroll
    for (int u = 0; u < 8; u++)
#pragma unroll
        for (int i = 0; i < 8; i++) acc[u][i] = 0.f;

    const float* Wh = W + head * D_IN * D_OUT;

    for (int k0 = 0; k0 < D_IN; k0 += 32) {
        __syncthreads();
#pragma unroll
        for (int u = 0; u < 4; u++) {
            int e4  = tid + u * 256;
            int row = e4 >> 3, kq = e4 & 7;
            float4 v = *(const float4*)&x[(rowbase + row) * D_IN + k0 + kq * 4];
            xs[kq * 4 + 0][row] = v.x;
            xs[kq * 4 + 1][row] = v.y;
            xs[kq * 4 + 2][row] = v.z;
            xs[kq * 4 + 3][row] = v.w;
        }
#pragma unroll
        for (int u = 0; u < 4; u++) {
            int e4 = tid + u * 256;
            int kk = e4 >> 5, oq = e4 & 31;
            *(float4*)&ws[kk][oq * 4] = *(const float4*)&Wh[(k0 + kk) * D_OUT + oq * 4];
        }
        __syncthreads();
#pragma unroll
        for (int kk = 0; kk < 32; kk++) {
            float wv[8];
            *(float4*)&wv[0] = *(const float4*)&ws[kk][o0];
            *(float4*)&wv[4] = *(const float4*)&ws[kk][o0 + 4];
#pragma unroll
            for (int u = 0; u < 8; u++) {
                float xv = xs[kk][ty + u * 16];
#pragma unroll
                for (int i = 0; i < 8; i++) acc[u][i] += xv * wv[i];
            }
        }
    }
#pragma unroll
    for (int u = 0; u < 8; u++) {
        int row = rowbase + ty + u * 16;
        float* dst = &g_h[(head * N_NODES + row) * D_OUT + o0];
        *(float4*)&dst[0] = make_float4(acc[u][0], acc[u][1], acc[u][2], acc[u][3]);
        *(float4*)&dst[4] = make_float4(acc[u][4], acc[u][5], acc[u][6], acc[u][7]);
    }
}

// ---------------- kernel 3: s_i, s_j and separable exp factors ----------------
__global__ void sij_kernel(const float* __restrict__ a) {
    int head = blockIdx.y;
    int warp = threadIdx.x >> 5, lane = threadIdx.x & 31;
    int row  = blockIdx.x * 8 + warp;
    const float* hrow = &g_h[(head * N_NODES + row) * D_OUT];
    const float* ah   = a + head * 2 * D_OUT;
    float s1 = 0.f, s2 = 0.f;
#pragma unroll
    for (int u = 0; u < 4; u++) {
        int o = lane + u * 32;
        float hv = hrow[o];
        s1 += hv * ah[o];
        s2 += hv * ah[D_OUT + o];
    }
#pragma unroll
    for (int off = 16; off; off >>= 1) {
        s1 += __shfl_xor_sync(0xffffffffu, s1, off);
        s2 += __shfl_xor_sync(0xffffffffu, s2, off);
    }
    if (lane == 0) {
        g_si [head * N_NODES + row] = s1;
        g_Ei [head * N_NODES + row] = expf(s1);
        g_Ei2[head * N_NODES + row] = expf(NEG_SLOPE * s1);
        g_jp [head * N_NODES + row] = make_float4(s2, expf(s2), expf(NEG_SLOPE * s2), 0.f);
    }
}

// ---------------- kernel 4: fused masked-softmax aggregation ----------------
// R1 reg budget (128 threads, 2 rows x 32 cols / thread, 32 u64 accs) with the
// bank-conflict fix applied to ADDRESSES only:
//   acc index  = 2*k, 2*k+1   (compile-time -> stays in registers)
//   LDS addr   = hrow + ((k + sh) & 7) * 4   (runtime uniform stagger)
// Per LDS.128, tx groups hit word offsets {4k,4k+8,4k+16,4k+24} mod 32 -> N=1.
__global__ __launch_bounds__(128) void agg_kernel(float* __restrict__ out) {
    __shared__ __align__(16) float  hsm[32 * 128];   // 32 j x 128 o tile
    __shared__ __align__(16) float4 psm[32];         // (sj, Ej, Ej2) per j

    int head    = blockIdx.y;
    int rowbase = blockIdx.x * 64;
    int tid = threadIdx.x;
    int tx  = tid & 3;
    int ty  = tid >> 2;
    int o0  = tx * 32;
    int sh  = tx * 2;                 // address stagger (uniform per thread)
    int r0  = rowbase + ty * 2, r1 = r0 + 1;

    float si0  = g_si [head * N_NODES + r0], si1  = g_si [head * N_NODES + r1];
    float Ei0  = g_Ei [head * N_NODES + r0], Ei1  = g_Ei [head * N_NODES + r1];
    float Ei20 = g_Ei2[head * N_NODES + r0], Ei21 = g_Ei2[head * N_NODES + r1];

    u64 acc0[16], acc1[16];
#pragma unroll
    for (int k = 0; k < 16; k++) { acc0[k] = 0ull; acc1[k] = 0ull; }
    float Z0 = 0.f, Z1 = 0.f;

    const float4* hsrc = (const float4*)&g_h[head * N_NODES * D_OUT];
    const float4* jpb  = &g_jp[head * N_NODES];

    for (int jt = 0; jt < N_NODES; jt += 32) {
        __syncthreads();
        {   // stage h tile (4096 floats = 1024 float4) + j params
            const float4* src = hsrc + jt * (D_OUT / 4);
            float4* dst = (float4*)hsm;
#pragma unroll
            for (int u = 0; u < 8; u++) dst[tid + u * 128] = src[tid + u * 128];
            if (tid < 32) psm[tid] = jpb[jt + tid];
        }
        __syncthreads();

        unsigned m0 = g_mask[r0 * NWORDS + (jt >> 5)];
        unsigned m1 = g_mask[r1 * NWORDS + (jt >> 5)];

#pragma unroll 8
        for (int jj = 0; jj < 32; jj++) {
            float4 p = psm[jj];
            float t0 = si0 + p.x;
            float v0 = (t0 > 0.f) ? (Ei0 * p.y) : (Ei20 * p.z);
            float w0 = ((m0 >> jj) & 1u) ? v0 : 0.f;
            float t1 = si1 + p.x;
            float v1 = (t1 > 0.f) ? (Ei1 * p.y) : (Ei21 * p.z);
            float w1 = ((m1 >> jj) & 1u) ? v1 : 0.f;
            Z0 += w0; Z1 += w1;
            u64 pw0 = packf2(w0, w0);
            u64 pw1 = packf2(w1, w1);
            const float* hrow = hsm + jj * 128 + o0;
#pragma unroll
            for (int k = 0; k < 8; k++) {
                // staggered ADDRESS, compile-time acc index
                ulonglong2 hv = *(const ulonglong2*)(hrow + (((k + sh) & 7) << 2));
                acc0[2 * k    ] = fma2(pw0, hv.x, acc0[2 * k    ]);
                acc0[2 * k + 1] = fma2(pw0, hv.y, acc0[2 * k + 1]);
                acc1[2 * k    ] = fma2(pw1, hv.x, acc1[2 * k    ]);
                acc1[2 * k + 1] = fma2(pw1, hv.y, acc1[2 * k + 1]);
            }
        }
    }

    float inv0 = 1.f / Z0, inv1 = 1.f / Z1;
    float* out0 = out + (u64)r0 * (H_HEADS * D_OUT) + head * D_OUT + o0;
    float* out1 = out + (u64)r1 * (H_HEADS * D_OUT) + head * D_OUT + o0;
#pragma unroll
    for (int k = 0; k < 8; k++) {
        int c4 = ((k + sh) & 7) << 2;     // de-rotate on store (runtime addr OK)
        float a0, b0, c0, d0, a1f, b1f, c1f, d1f;
        unpackf2(acc0[2 * k],     a0, b0);
        unpackf2(acc0[2 * k + 1], c0, d0);
        unpackf2(acc1[2 * k],     a1f, b1f);
        unpackf2(acc1[2 * k + 1], c1f, d1f);
        *(float4*)&out0[c4] = make_float4(a0 * inv0, b0 * inv0, c0 * inv0, d0 * inv0);
        *(float4*)&out1[c4] = make_float4(a1f * inv1, b1f * inv1, c1f * inv1, d1f * inv1);
    }
}

// ---------------- launch ----------------
extern "C" void kernel_launch(void* const* d_in, const int* in_sizes, int n_in,
                              void* d_out, int out_size) {
    const float* x = (const float*)d_in[0];
    const int*   A = (const int*)  d_in[1];
    const float* W = (const float*)d_in[2];
    const float* a = (const float*)d_in[3];
    float* out = (float*)d_out;

    pack_mask_kernel<<<(N_NODES * N_NODES) / 256, 256>>>(A);
    h_gemm_kernel<<<dim3(N_NODES / 128, H_HEADS), 256>>>(x, W);
    sij_kernel<<<dim3(N_NODES / 8, H_HEADS), 256>>>(a);
    agg_kernel<<<dim3(N_NODES / 64, H_HEADS), 128>>>(out);
}

// round 7
// speedup vs baseline: 37.8778x; 1.1786x over previous
#include <cuda_runtime.h>
#include <cstdint>

#define N_NODES 4096
#define D_IN    256
#define D_OUT   128
#define H_HEADS 4
#define NEG_SLOPE 0.2f
#define NWORDS  (N_NODES / 32)

typedef unsigned long long u64;

// ---------------- scratch (device globals; no allocation allowed) ----------------
__device__ float    g_h[H_HEADS * N_NODES * D_OUT];   // 8 MB   h[head][j][o]
__device__ unsigned g_mask[N_NODES * NWORDS];          // 2 MB   bit j of row i
__device__ float    g_si [H_HEADS * N_NODES];
__device__ float    g_Ei [H_HEADS * N_NODES];          // exp(s_i)
__device__ float    g_Ei2[H_HEADS * N_NODES];          // exp(0.2*s_i)
__device__ float4   g_jp [H_HEADS * N_NODES];          // (s_j, exp(s_j), exp(0.2*s_j), 0)

// ---------------- f32x2 helpers (Blackwell packed fp32) ----------------
__device__ __forceinline__ u64 packf2(float lo, float hi) {
    u64 r; asm("mov.b64 %0, {%1, %2};" : "=l"(r) : "f"(lo), "f"(hi)); return r;
}
__device__ __forceinline__ void unpackf2(u64 v, float& lo, float& hi) {
    asm("mov.b64 {%0, %1}, %2;" : "=f"(lo), "=f"(hi) : "l"(v));
}
__device__ __forceinline__ u64 fma2(u64 a, u64 b, u64 c) {
    u64 r; asm("fma.rn.f32x2 %0, %1, %2, %3;" : "=l"(r) : "l"(a), "l"(b), "l"(c)); return r;
}

// ---------------- kernel 1: bit-pack mask = (A>0) | eye ----------------
__global__ void pack_mask_kernel(const int* __restrict__ A) {
    int g    = blockIdx.x * blockDim.x + threadIdx.x;
    int lane = g & 31;
    int word = g >> 5;
    int row  = word >> 7;
    int jw   = word & 127;
    int j    = jw * 32 + lane;
    int v = (A[row * N_NODES + j] > 0) || (j == row);
    unsigned b = __ballot_sync(0xffffffffu, v);
    if (lane == 0) g_mask[word] = b;
}

// ---------------- kernel 2: h = x @ W per head (fp32 tiled GEMM) ----------------
__global__ __launch_bounds__(256) void h_gemm_kernel(const float* __restrict__ x,
                                                     const float* __restrict__ W) {
    __shared__ __align__(16) float xs[32][129];
    __shared__ __align__(16) float ws[32][128];
    int head    = blockIdx.y;
    int rowbase = blockIdx.x * 128;
    int tid = threadIdx.x;
    int tx  = tid & 15;
    int ty  = tid >> 4;
    int o0  = tx * 8;

    float acc[8][8];
#pragma unroll
    for (int u = 0; u < 8; u++)
#pragma unroll
        for (int i = 0; i < 8; i++) acc[u][i] = 0.f;

    const float* Wh = W + head * D_IN * D_OUT;

    for (int k0 = 0; k0 < D_IN; k0 += 32) {
        __syncthreads();
#pragma unroll
        for (int u = 0; u < 4; u++) {
            int e4  = tid + u * 256;
            int row = e4 >> 3, kq = e4 & 7;
            float4 v = *(const float4*)&x[(rowbase + row) * D_IN + k0 + kq * 4];
            xs[kq * 4 + 0][row] = v.x;
            xs[kq * 4 + 1][row] = v.y;
            xs[kq * 4 + 2][row] = v.z;
            xs[kq * 4 + 3][row] = v.w;
        }
#pragma unroll
        for (int u = 0; u < 4; u++) {
            int e4 = tid + u * 256;
            int kk = e4 >> 5, oq = e4 & 31;
            *(float4*)&ws[kk][oq * 4] = *(const float4*)&Wh[(k0 + kk) * D_OUT + oq * 4];
        }
        __syncthreads();
#pragma unroll
        for (int kk = 0; kk < 32; kk++) {
            float wv[8];
            *(float4*)&wv[0] = *(const float4*)&ws[kk][o0];
            *(float4*)&wv[4] = *(const float4*)&ws[kk][o0 + 4];
#pragma unroll
            for (int u = 0; u < 8; u++) {
                float xv = xs[kk][ty + u * 16];
#pragma unroll
                for (int i = 0; i < 8; i++) acc[u][i] += xv * wv[i];
            }
        }
    }
#pragma unroll
    for (int u = 0; u < 8; u++) {
        int row = rowbase + ty + u * 16;
        float* dst = &g_h[(head * N_NODES + row) * D_OUT + o0];
        *(float4*)&dst[0] = make_float4(acc[u][0], acc[u][1], acc[u][2], acc[u][3]);
        *(float4*)&dst[4] = make_float4(acc[u][4], acc[u][5], acc[u][6], acc[u][7]);
    }
}

// ---------------- kernel 3: s_i, s_j and separable exp factors ----------------
__global__ void sij_kernel(const float* __restrict__ a) {
    int head = blockIdx.y;
    int warp = threadIdx.x >> 5, lane = threadIdx.x & 31;
    int row  = blockIdx.x * 8 + warp;
    const float* hrow = &g_h[(head * N_NODES + row) * D_OUT];
    const float* ah   = a + head * 2 * D_OUT;
    float s1 = 0.f, s2 = 0.f;
#pragma unroll
    for (int u = 0; u < 4; u++) {
        int o = lane + u * 32;
        float hv = hrow[o];
        s1 += hv * ah[o];
        s2 += hv * ah[D_OUT + o];
    }
#pragma unroll
    for (int off = 16; off; off >>= 1) {
        s1 += __shfl_xor_sync(0xffffffffu, s1, off);
        s2 += __shfl_xor_sync(0xffffffffu, s2, off);
    }
    if (lane == 0) {
        g_si [head * N_NODES + row] = s1;
        g_Ei [head * N_NODES + row] = expf(s1);
        g_Ei2[head * N_NODES + row] = expf(NEG_SLOPE * s1);
        g_jp [head * N_NODES + row] = make_float4(s2, expf(s2), expf(NEG_SLOPE * s2), 0.f);
    }
}

// ---------------- kernel 4: fused masked-softmax aggregation (v4) ----------------
// 128 threads, 64 rows/block. Per thread: 4 rows x 16 cols.
//   tx = tid & 7  -> o0 = tx*16, stagger sh = tx>>1
//   ty = tid >> 3 -> rows r0..r0+3 (r0 = rowbase + ty*4)
// Per jj: 4 LDS.128 (staggered addresses, conflict-free: chunk (4tx + (k+sh)&3)
// mod 8 is a permutation of 0..7) and 32 fma2 -> fma-pipe-bound (8 fma2 : 1 LDS).
// Acc indices stay compile-time (spill discipline from R4).
__global__ __launch_bounds__(128) void agg_kernel(float* __restrict__ out) {
    __shared__ __align__(16) float  hsm[32 * 128];   // 32 j x 128 o tile
    __shared__ __align__(16) float4 psm[32];         // (sj, Ej, Ej2) per j

    int head    = blockIdx.y;
    int rowbase = blockIdx.x * 64;
    int tid = threadIdx.x;
    int tx  = tid & 7;
    int ty  = tid >> 3;
    int o0  = tx * 16;
    int sh  = tx >> 1;                // address stagger (0..3)
    int r0  = rowbase + ty * 4;

    float si[4], Ei[4], Ei2[4], Z[4];
#pragma unroll
    for (int u = 0; u < 4; u++) {
        si [u] = g_si [head * N_NODES + r0 + u];
        Ei [u] = g_Ei [head * N_NODES + r0 + u];
        Ei2[u] = g_Ei2[head * N_NODES + r0 + u];
        Z  [u] = 0.f;
    }

    u64 acc[4][8];                    // 32 u64 = 64 regs (R6-proven budget)
#pragma unroll
    for (int u = 0; u < 4; u++)
#pragma unroll
        for (int k = 0; k < 8; k++) acc[u][k] = 0ull;

    const float4* hsrc = (const float4*)&g_h[head * N_NODES * D_OUT];
    const float4* jpb  = &g_jp[head * N_NODES];

    for (int jt = 0; jt < N_NODES; jt += 32) {
        __syncthreads();
        {   // stage 32x128 h tile = 1024 float4, 8 per thread (coalesced)
            const float4* src = hsrc + jt * (D_OUT / 4);
            float4* dst = (float4*)hsm;
#pragma unroll
            for (int u = 0; u < 8; u++) dst[tid + u * 128] = src[tid + u * 128];
            if (tid < 32) psm[tid] = jpb[jt + tid];
        }
        __syncthreads();

        unsigned m[4];
#pragma unroll
        for (int u = 0; u < 4; u++) m[u] = g_mask[(r0 + u) * NWORDS + (jt >> 5)];

#pragma unroll 4
        for (int jj = 0; jj < 32; jj++) {
            float4 p = psm[jj];
            u64 pw[4];
#pragma unroll
            for (int u = 0; u < 4; u++) {
                float t = si[u] + p.x;
                float v = (t > 0.f) ? (Ei[u] * p.y) : (Ei2[u] * p.z);
                float w = ((m[u] >> jj) & 1u) ? v : 0.f;
                Z[u] += w;
                pw[u] = packf2(w, w);
            }
            const float* hrow = hsm + jj * 128 + o0;
#pragma unroll
            for (int k = 0; k < 4; k++) {
                // staggered ADDRESS, compile-time acc index
                ulonglong2 hv = *(const ulonglong2*)(hrow + (((k + sh) & 3) << 2));
#pragma unroll
                for (int u = 0; u < 4; u++) {
                    acc[u][2 * k    ] = fma2(pw[u], hv.x, acc[u][2 * k    ]);
                    acc[u][2 * k + 1] = fma2(pw[u], hv.y, acc[u][2 * k + 1]);
                }
            }
        }
    }

#pragma unroll
    for (int u = 0; u < 4; u++) {
        float inv = 1.f / Z[u];
        float* dst = out + (u64)(r0 + u) * (H_HEADS * D_OUT) + head * D_OUT + o0;
#pragma unroll
        for (int k = 0; k < 4; k++) {
            int c4 = ((k + sh) & 3) << 2;     // de-rotate on store
            float f0, f1, f2, f3;
            unpackf2(acc[u][2 * k],     f0, f1);
            unpackf2(acc[u][2 * k + 1], f2, f3);
            *(float4*)&dst[c4] = make_float4(f0 * inv, f1 * inv, f2 * inv, f3 * inv);
        }
    }
}

// ---------------- launch ----------------
extern "C" void kernel_launch(void* const* d_in, const int* in_sizes, int n_in,
                              void* d_out, int out_size) {
    const float* x = (const float*)d_in[0];
    const int*   A = (const int*)  d_in[1];
    const float* W = (const float*)d_in[2];
    const float* a = (const float*)d_in[3];
    float* out = (float*)d_out;

    pack_mask_kernel<<<(N_NODES * N_NODES) / 256, 256>>>(A);
    h_gemm_kernel<<<dim3(N_NODES / 128, H_HEADS), 256>>>(x, W);
    sij_kernel<<<dim3(N_NODES / 8, H_HEADS), 256>>>(a);
    agg_kernel<<<dim3(N_NODES / 64, H_HEADS), 128>>>(out);
}

// round 8
// speedup vs baseline: 38.6573x; 1.0206x over previous
#include <cuda_runtime.h>
#include <cstdint>

#define N_NODES 4096
#define D_IN    256
#define D_OUT   128
#define H_HEADS 4
#define NEG_SLOPE 0.2f
#define NWORDS  (N_NODES / 32)

typedef unsigned long long u64;

// ---------------- scratch (device globals; no allocation allowed) ----------------
__device__ float    g_h[H_HEADS * N_NODES * D_OUT];   // 8 MB   h[head][j][o]
__device__ unsigned g_mask[N_NODES * NWORDS];          // 2 MB
__device__ float    g_Ei [H_HEADS * N_NODES];          // exp(s_i)
__device__ float    g_Ei2[H_HEADS * N_NODES];          // exp(0.2*s_i)
__device__ float2   g_jp [H_HEADS * N_NODES];          // (exp(s_j), exp(0.2*s_j))
__device__ float    g_part[2 * H_HEADS * N_NODES * D_OUT];  // 16 MB partial sums
__device__ float    g_Zp  [2 * H_HEADS * N_NODES];          // partial Z

// ---------------- f32x2 helpers (Blackwell packed fp32) ----------------
__device__ __forceinline__ u64 packf2(float lo, float hi) {
    u64 r; asm("mov.b64 %0, {%1, %2};" : "=l"(r) : "f"(lo), "f"(hi)); return r;
}
__device__ __forceinline__ void unpackf2(u64 v, float& lo, float& hi) {
    asm("mov.b64 {%0, %1}, %2;" : "=f"(lo), "=f"(hi) : "l"(v));
}
__device__ __forceinline__ u64 fma2(u64 a, u64 b, u64 c) {
    u64 r; asm("fma.rn.f32x2 %0, %1, %2, %3;" : "=l"(r) : "l"(a), "l"(b), "l"(c)); return r;
}

// ---------------- kernel 1: bit-pack mask = (A>0) | eye ----------------
__global__ void pack_mask_kernel(const int* __restrict__ A) {
    int g    = blockIdx.x * blockDim.x + threadIdx.x;
    int lane = g & 31;
    int word = g >> 5;
    int row  = word >> 7;
    int jw   = word & 127;
    int j    = jw * 32 + lane;
    int v = (A[row * N_NODES + j] > 0) || (j == row);
    unsigned b = __ballot_sync(0xffffffffu, v);
    if (lane == 0) g_mask[word] = b;
}

// ---------------- kernel 2: h = x @ W per head (fp32 tiled GEMM) ----------------
__global__ __launch_bounds__(256) void h_gemm_kernel(const float* __restrict__ x,
                                                     const float* __restrict__ W) {
    __shared__ __align__(16) float xs[32][129];
    __shared__ __align__(16) float ws[32][128];
    int head    = blockIdx.y;
    int rowbase = blockIdx.x * 128;
    int tid = threadIdx.x;
    int tx  = tid & 15;
    int ty  = tid >> 4;
    int o0  = tx * 8;

    float acc[8][8];
#pragma unroll
    for (int u = 0; u < 8; u++)
#pragma unroll
        for (int i = 0; i < 8; i++) acc[u][i] = 0.f;

    const float* Wh = W + head * D_IN * D_OUT;

    for (int k0 = 0; k0 < D_IN; k0 += 32) {
        __syncthreads();
#pragma unroll
        for (int u = 0; u < 4; u++) {
            int e4  = tid + u * 256;
            int row = e4 >> 3, kq = e4 & 7;
            float4 v = *(const float4*)&x[(rowbase + row) * D_IN + k0 + kq * 4];
            xs[kq * 4 + 0][row] = v.x;
            xs[kq * 4 + 1][row] = v.y;
            xs[kq * 4 + 2][row] = v.z;
            xs[kq * 4 + 3][row] = v.w;
        }
#pragma unroll
        for (int u = 0; u < 4; u++) {
            int e4 = tid + u * 256;
            int kk = e4 >> 5, oq = e4 & 31;
            *(float4*)&ws[kk][oq * 4] = *(const float4*)&Wh[(k0 + kk) * D_OUT + oq * 4];
        }
        __syncthreads();
#pragma unroll
        for (int kk = 0; kk < 32; kk++) {
            float wv[8];
            *(float4*)&wv[0] = *(const float4*)&ws[kk][o0];
            *(float4*)&wv[4] = *(const float4*)&ws[kk][o0 + 4];
#pragma unroll
            for (int u = 0; u < 8; u++) {
                float xv = xs[kk][ty + u * 16];
#pragma unroll
                for (int i = 0; i < 8; i++) acc[u][i] += xv * wv[i];
            }
        }
    }
#pragma unroll
    for (int u = 0; u < 8; u++) {
        int row = rowbase + ty + u * 16;
        float* dst = &g_h[(head * N_NODES + row) * D_OUT + o0];
        *(float4*)&dst[0] = make_float4(acc[u][0], acc[u][1], acc[u][2], acc[u][3]);
        *(float4*)&dst[4] = make_float4(acc[u][4], acc[u][5], acc[u][6], acc[u][7]);
    }
}

// ---------------- kernel 3: s_i, s_j and separable exp factors ----------------
__global__ void sij_kernel(const float* __restrict__ a) {
    int head = blockIdx.y;
    int warp = threadIdx.x >> 5, lane = threadIdx.x & 31;
    int row  = blockIdx.x * 8 + warp;
    const float* hrow = &g_h[(head * N_NODES + row) * D_OUT];
    const float* ah   = a + head * 2 * D_OUT;
    float s1 = 0.f, s2 = 0.f;
#pragma unroll
    for (int u = 0; u < 4; u++) {
        int o = lane + u * 32;
        float hv = hrow[o];
        s1 += hv * ah[o];
        s2 += hv * ah[D_OUT + o];
    }
#pragma unroll
    for (int off = 16; off; off >>= 1) {
        s1 += __shfl_xor_sync(0xffffffffu, s1, off);
        s2 += __shfl_xor_sync(0xffffffffu, s2, off);
    }
    if (lane == 0) {
        g_Ei [head * N_NODES + row] = expf(s1);
        g_Ei2[head * N_NODES + row] = expf(NEG_SLOPE * s1);
        g_jp [head * N_NODES + row] = make_float2(expf(s2), expf(NEG_SLOPE * s2));
    }
}

// ---------------- kernel 4: masked-softmax aggregation, j-split partials -------
// Grid (64, 4, 2): 64 rows x one head x one j-half per block; 128 threads.
// Per thread: 4 rows x 16 cols; 4 LDS.128 : 32 fma2 per jj.
// Weight: v = fmax(Ei*Ej, Ei2*Ej2)  (exact: e^t vs e^{0.2t} cross at t=0).
// Writes UNNORMALIZED partial sums + partial Z; normalize_kernel combines.
__global__ __launch_bounds__(128) void agg_kernel() {
    __shared__ __align__(16) float  hsm[32 * 128];
    __shared__ __align__(16) float2 psm[32];

    int head    = blockIdx.y;
    int half    = blockIdx.z;
    int rowbase = blockIdx.x * 64;
    int tid = threadIdx.x;
    int tx  = tid & 7;
    int ty  = tid >> 3;
    int o0  = tx * 16;
    int sh  = tx >> 1;
    int r0  = rowbase + ty * 4;

    float Ei[4], Ei2[4], Z[4];
#pragma unroll
    for (int u = 0; u < 4; u++) {
        Ei [u] = g_Ei [head * N_NODES + r0 + u];
        Ei2[u] = g_Ei2[head * N_NODES + r0 + u];
        Z  [u] = 0.f;
    }

    u64 acc[4][8];
#pragma unroll
    for (int u = 0; u < 4; u++)
#pragma unroll
        for (int k = 0; k < 8; k++) acc[u][k] = 0ull;

    const float4* hsrc = (const float4*)&g_h[head * N_NODES * D_OUT];
    const float2* jpb  = &g_jp[head * N_NODES];

    int jbeg = half * (N_NODES / 2);
    int jend = jbeg + (N_NODES / 2);

    for (int jt = jbeg; jt < jend; jt += 32) {
        __syncthreads();
        {
            const float4* src = hsrc + jt * (D_OUT / 4);
            float4* dst = (float4*)hsm;
#pragma unroll
            for (int u = 0; u < 8; u++) dst[tid + u * 128] = src[tid + u * 128];
            if (tid < 32) psm[tid] = jpb[jt + tid];
        }
        __syncthreads();

        unsigned m[4];
#pragma unroll
        for (int u = 0; u < 4; u++) m[u] = g_mask[(r0 + u) * NWORDS + (jt >> 5)];

#pragma unroll 4
        for (int jj = 0; jj < 32; jj++) {
            float2 p = psm[jj];
            u64 pw[4];
#pragma unroll
            for (int u = 0; u < 4; u++) {
                float v = fmaxf(Ei[u] * p.x, Ei2[u] * p.y);
                float w = ((m[u] >> jj) & 1u) ? v : 0.f;
                Z[u] += w;
                pw[u] = packf2(w, w);
            }
            const float* hrow = hsm + jj * 128 + o0;
#pragma unroll
            for (int k = 0; k < 4; k++) {
                ulonglong2 hv = *(const ulonglong2*)(hrow + (((k + sh) & 3) << 2));
#pragma unroll
                for (int u = 0; u < 4; u++) {
                    acc[u][2 * k    ] = fma2(pw[u], hv.x, acc[u][2 * k    ]);
                    acc[u][2 * k + 1] = fma2(pw[u], hv.y, acc[u][2 * k + 1]);
                }
            }
        }
    }

    int base = (half * H_HEADS + head) * N_NODES;
#pragma unroll
    for (int u = 0; u < 4; u++) {
        float* dst = &g_part[(u64)(base + r0 + u) * D_OUT + o0];
        if (tx == 0) g_Zp[base + r0 + u] = Z[u];
#pragma unroll
        for (int k = 0; k < 4; k++) {
            int c4 = ((k + sh) & 3) << 2;     // de-rotate on store
            float f0, f1, f2, f3;
            unpackf2(acc[u][2 * k],     f0, f1);
            unpackf2(acc[u][2 * k + 1], f2, f3);
            *(float4*)&dst[c4] = make_float4(f0, f1, f2, f3);
        }
    }
}

// ---------------- kernel 5: combine halves + softmax normalize ----------------
__global__ void normalize_kernel(float* __restrict__ out) {
    int t    = blockIdx.x * blockDim.x + threadIdx.x;     // 524288 float4s
    int o4   = t & 31;            // float4 index within 128 cols
    int head = (t >> 5) & 3;
    int row  = t >> 7;

    int b0 = head * N_NODES + row;
    int b1 = (H_HEADS + head) * N_NODES + row;
    float Zt = g_Zp[b0] + g_Zp[b1];
    float inv = 1.f / Zt;

    float4 p0 = *(const float4*)&g_part[(u64)b0 * D_OUT + o4 * 4];
    float4 p1 = *(const float4*)&g_part[(u64)b1 * D_OUT + o4 * 4];
    float4 r = make_float4((p0.x + p1.x) * inv, (p0.y + p1.y) * inv,
                           (p0.z + p1.z) * inv, (p0.w + p1.w) * inv);
    *(float4*)&out[(u64)row * 512 + head * D_OUT + o4 * 4] = r;
}

// ---------------- launch ----------------
extern "C" void kernel_launch(void* const* d_in, const int* in_sizes, int n_in,
                              void* d_out, int out_size) {
    const float* x = (const float*)d_in[0];
    const int*   A = (const int*)  d_in[1];
    const float* W = (const float*)d_in[2];
    const float* a = (const float*)d_in[3];
    float* out = (float*)d_out;

    pack_mask_kernel<<<(N_NODES * N_NODES) / 256, 256>>>(A);
    h_gemm_kernel<<<dim3(N_NODES / 128, H_HEADS), 256>>>(x, W);
    sij_kernel<<<dim3(N_NODES / 8, H_HEADS), 256>>>(a);
    agg_kernel<<<dim3(N_NODES / 64, H_HEADS, 2), 128>>>();
    normalize_kernel<<<(N_NODES * H_HEADS * (D_OUT / 4)) / 256, 256>>>(out);
}